// round 11
// baseline (speedup 1.0000x reference)
#include <cuda_runtime.h>
#include <cstdint>

// DynamicDownsampling: out[b,c,h,w] = softmax_p(kernel[b,p,h,w]) . x_edgepad 5x5
// x:[4,32,256,256] f32, kernel:[4,25,256,256] f32. Weights channel-invariant.
// Scalar-C++ version: 1x2 px/thread (50 weight regs), NO inline-asm packing
// (the ull/pack2/lo2/hi2 idiom was costing ~2x dynamic MOVs), 256 thr at
// __launch_bounds__(256,3) -> ~24 warps/SM (2.3x prior residency).

#define KS   5
#define PAD  2
#define KK   25
#define H    256
#define W    256
#define C    32
#define B    4
#define HW   (H*W)

#define TDX  32                   // output tile width
#define TDY  16                   // output tile height
#define ROWS (TDY + 2*PAD)        // 20 staged rows
#define COLM 40                   // padded smem row width (floats); data cols 2..37
#define TILE_F (ROWS*COLM)        // 800 floats / channel
#define TILE_B (TILE_F*4)         // 3200 bytes

#define NTHREADS 256              // 16 x-pairs x 16 rows
#define NC   4                    // channels per stage
#define NG   (C/NC)               // 8
#define NBUF 2

#define SLOTS_PER_ROW 12          // 8 x 16B interior + 4 x 4B halo
#define SLOTS (ROWS*SLOTS_PER_ROW)  // 240 (<= 256 threads, 1 slot each)

__device__ __forceinline__ uint32_t smem_u32(const void* p) {
    uint32_t a;
    asm("{ .reg .u64 t; cvta.to.shared.u64 t, %1; cvt.u32.u64 %0, t; }" : "=r"(a) : "l"(p));
    return a;
}
__device__ __forceinline__ void cp_async16(uint32_t dst, const float* src) {
    asm volatile("cp.async.cg.shared.global [%0], [%1], 16;\n" :: "r"(dst), "l"(src));
}
__device__ __forceinline__ void cp_async4(uint32_t dst, const float* src) {
    asm volatile("cp.async.ca.shared.global [%0], [%1], 4;\n" :: "r"(dst), "l"(src));
}
__device__ __forceinline__ void cp_commit() { asm volatile("cp.async.commit_group;\n"); }
template<int N> __device__ __forceinline__ void cp_wait() {
    asm volatile("cp.async.wait_group %0;\n" :: "n"(N));
}

__global__ __launch_bounds__(NTHREADS, 3)
void dds_kernel(const float* __restrict__ x,
                const float* __restrict__ kern,
                float* __restrict__ out)
{
    __shared__ float tile[NBUF][NC][TILE_F];   // 25600 B

    const int tid = threadIdx.x;
    const int txp = tid & 15;     // pixel-pair index in x
    const int ty  = tid >> 4;     // output row 0..15

    const int bx = blockIdx.x, by = blockIdx.y, b = blockIdx.z;
    const int x0 = bx * TDX;
    const int y0 = by * TDY - PAD;

    const float* xb = x   + (size_t)b * C * HW;
    float*       ob = out + (size_t)b * C * HW;

    // ---- per-thread staging slot (one, same pattern every group) ----
    const bool v0 = tid < SLOTS;
    int soff = 0; uint32_t doff = 0; bool is16 = true;
    {
        int s = v0 ? tid : 0;
        const int r = s / SLOTS_PER_ROW;
        const int k = s - r * SLOTS_PER_ROW;
        int yy = y0 + r; yy = yy < 0 ? 0 : (yy > H-1 ? H-1 : yy);
        if (k < 8) {
            is16 = true;
            soff = yy * W + x0 + k * 4;
            doff = (uint32_t)(r * (COLM*4) + 16 + k * 16);
        } else {
            is16 = false;
            const int kk2 = k - 8;
            const int scol = (kk2 < 2) ? (2 + kk2) : (36 + kk2 - 2);
            int gxp = x0 + ((kk2 < 2) ? (kk2 - 2) : (32 + kk2 - 2));
            gxp = gxp < 0 ? 0 : (gxp > W-1 ? W-1 : gxp);
            soff = yy * W + gxp;
            doff = (uint32_t)(r * (COLM*4) + scol * 4);
        }
    }

    const uint32_t sbase = smem_u32(&tile[0][0][0]);
    const uint32_t buf_bytes = (uint32_t)(NC * TILE_B);

    // ---- stage group 0 (overlaps weight softmax below) ----
    if (v0) {
        #pragma unroll
        for (int c = 0; c < NC; ++c) {
            const float* src = xb + (size_t)c * HW;
            const uint32_t db = sbase + (uint32_t)c * TILE_B;
            if (is16) cp_async16(db + doff, src + soff);
            else      cp_async4 (db + doff, src + soff);
        }
    }
    cp_commit();

    // ---- softmax weights for the 2 pixels (plain scalar fp32) ----
    const int gx0 = x0 + 2 * txp;
    const int gy0 = by * TDY + ty;
    const float2* kp = (const float2*)(kern + ((size_t)b * KK) * HW + (size_t)gy0 * W + gx0);

    float wA[KK], wB[KK];
    float m0 = -1e30f, m1 = -1e30f;
    #pragma unroll
    for (int p = 0; p < KK; ++p) {
        float2 a = kp[(size_t)p * (HW/2)];
        wA[p] = a.x; wB[p] = a.y;
        m0 = fmaxf(m0, a.x); m1 = fmaxf(m1, a.y);
    }
    float s0 = 0.f, s1 = 0.f;
    #pragma unroll
    for (int p = 0; p < KK; ++p) {
        wA[p] = __expf(wA[p] - m0); s0 += wA[p];
        wB[p] = __expf(wB[p] - m1); s1 += wB[p];
    }
    {
        const float i0 = 1.f/s0, i1 = 1.f/s1;
        #pragma unroll
        for (int p = 0; p < KK; ++p) { wA[p] *= i0; wB[p] *= i1; }
    }

    float2* obq = (float2*)(ob + (size_t)gy0 * W + gx0);
    const int qbase = ty * COLM + (2*txp + 2);   // smem window base (floats)

    // ---- double-buffered channel-group loop ----
    for (int g = 0; g < NG; ++g) {
        const int buf = g & 1;

        __syncthreads();   // readers of buf^1 done before overwrite

        if (g + 1 < NG) {
            const float* srcg = xb + (size_t)(g + 1) * NC * HW;
            const uint32_t db0 = sbase + (uint32_t)(buf ^ 1) * buf_bytes;
            if (v0) {
                #pragma unroll
                for (int c = 0; c < NC; ++c) {
                    const float* src = srcg + (size_t)c * HW;
                    const uint32_t db = db0 + (uint32_t)c * TILE_B;
                    if (is16) cp_async16(db + doff, src + soff);
                    else      cp_async4 (db + doff, src + soff);
                }
            }
            cp_commit();
            cp_wait<1>();   // group g complete (g+1 pending)
        } else {
            cp_wait<0>();
        }
        __syncthreads();

        const float* tb = &tile[buf][0][0] + qbase;
        #pragma unroll
        for (int c = 0; c < NC; ++c) {
            const float* t = tb + c * TILE_F;
            // 4 independent scalar chains (2 per output pixel)
            float a0 = 0.f, b0 = 0.f, a1 = 0.f, b1 = 0.f;
            #pragma unroll
            for (int dr = 0; dr < KS; ++dr) {
                const float2* rp = (const float2*)(t + dr * COLM);   // 8B aligned
                const float2 p0 = rp[0], p1 = rp[1], p2 = rp[2];     // d0..d5
                const int pb = dr * KS;
                a0 = fmaf(wA[pb+0], p0.x, a0);   a1 = fmaf(wB[pb+0], p0.y, a1);
                b0 = fmaf(wA[pb+1], p0.y, b0);   b1 = fmaf(wB[pb+1], p1.x, b1);
                a0 = fmaf(wA[pb+2], p1.x, a0);   a1 = fmaf(wB[pb+2], p1.y, a1);
                b0 = fmaf(wA[pb+3], p1.y, b0);   b1 = fmaf(wB[pb+3], p2.x, b1);
                a0 = fmaf(wA[pb+4], p2.x, a0);   a1 = fmaf(wB[pb+4], p2.y, a1);
            }
            float2 o; o.x = a0 + b0; o.y = a1 + b1;
            obq[(size_t)(g * NC + c) * (HW/2)] = o;   // STG.64
        }
    }
}

extern "C" void kernel_launch(void* const* d_in, const int* in_sizes, int n_in,
                              void* d_out, int out_size)
{
    const float* x    = (const float*)d_in[0];
    const float* kern = (const float*)d_in[1];
    float*       out  = (float*)d_out;

    dim3 grid(W / TDX, H / TDY, B);   // (8,16,4) = 512 blocks
    dds_kernel<<<grid, NTHREADS>>>(x, kern, out);
}